// round 10
// baseline (speedup 1.0000x reference)
#include <cuda_runtime.h>

// out = y where 0 < y <= 1 else 0, y = x * w[col] + b[col]
// x: [8192, 4096] f32, w/b: [4096] f32. HBM-bound elementwise.
// R10: winning R2 recipe (ITEMS=4 front-batched streaming x reads, JIT w/b,
//      streaming stores) with THREADS=512 / chunk=2048 / grid=4096 — final
//      block-geometry probe. All other axes proven neutral in R3-R9; kernel
//      is pinned at the mixed read+write DRAM ceiling (~7 TB/s wall-clock).

#define D_VEC 1024            // 4096 / 4, power of two
#define ITEMS 4               // float4s per thread
#define THREADS 512
#define CHUNK (THREADS * ITEMS)   // 2048 float4 per block (2 rows' worth)

__device__ __forceinline__ float4 gate4(float4 xv, float4 wv, float4 bv)
{
    float4 y;
    y.x = fmaf(xv.x, wv.x, bv.x);
    y.y = fmaf(xv.y, wv.y, bv.y);
    y.z = fmaf(xv.z, wv.z, bv.z);
    y.w = fmaf(xv.w, wv.w, bv.w);
    y.x = (y.x > 0.0f && y.x <= 1.0f) ? y.x : 0.0f;
    y.y = (y.y > 0.0f && y.y <= 1.0f) ? y.y : 0.0f;
    y.z = (y.z > 0.0f && y.z <= 1.0f) ? y.z : 0.0f;
    y.w = (y.w > 0.0f && y.w <= 1.0f) ? y.w : 0.0f;
    return y;
}

__global__ void __launch_bounds__(THREADS)
gegate_kernel(const float4* __restrict__ x,
              const float4* __restrict__ w,
              const float4* __restrict__ b,
              float4* __restrict__ out)
{
    // Each block covers CHUNK consecutive float4s; thread t handles
    // base + i*THREADS (fully coalesced, 4 independent DRAM loads in flight).
    int base = blockIdx.x * CHUNK + threadIdx.x;

    float4 xv[ITEMS];
    #pragma unroll
    for (int i = 0; i < ITEMS; i++)
        xv[i] = __ldcs(&x[base + i * THREADS]);   // streaming: no L2 reuse

    #pragma unroll
    for (int i = 0; i < ITEMS; i++) {
        int idx = base + i * THREADS;
        int col = idx & (D_VEC - 1);
        float4 wv = __ldg(&w[col]);
        float4 bv = __ldg(&b[col]);
        __stcs(&out[idx], gate4(xv[i], wv, bv));
    }
}

extern "C" void kernel_launch(void* const* d_in, const int* in_sizes, int n_in,
                              void* d_out, int out_size)
{
    const float4* x = (const float4*)d_in[0];
    const float4* w = (const float4*)d_in[1];
    const float4* b = (const float4*)d_in[2];
    float4* out = (float4*)d_out;

    int n_vec = out_size / 4;                     // 8388608
    int blocks = n_vec / CHUNK;                   // 4096 exactly

    gegate_kernel<<<blocks, THREADS>>>(x, w, b, out);
}